// round 2
// baseline (speedup 1.0000x reference)
#include <cuda_runtime.h>
#include <math.h>

#define N_LEVELS      16
#define HASHMAP_SIZE  (1u << 19)
#define HASH_MASK     (HASHMAP_SIZE - 1u)
#define P2            2654435761u
#define P3            805459861u

struct ResTable {
    int res[N_LEVELS];
};

__device__ __forceinline__ float2 lo2(float4 q) { return make_float2(q.x, q.y); }
__device__ __forceinline__ float2 hi2(float4 q) { return make_float2(q.z, q.w); }

__global__ void __launch_bounds__(256)
hashenc_kernel(const float* __restrict__ pos,
               const float* __restrict__ emb,
               float* __restrict__ out,
               ResTable rt,
               int n_points)
{
    int p = blockIdx.x * blockDim.x + threadIdx.x;
    if (p >= n_points) return;

    const float px = pos[p * 3 + 0];
    const float py = pos[p * 3 + 1];
    const float pz = pos[p * 3 + 2];

    float result[2 * N_LEVELS];

#pragma unroll
    for (int l = 0; l < N_LEVELS; ++l) {
        const int   res  = rt.res[l];
        const float fres = (float)res;

        const float sx = px * fres, sy = py * fres, sz = pz * fres;
        const float fx = floorf(sx), fy = floorf(sy), fz = floorf(sz);
        const int   vx = (int)fx,   vy = (int)fy,   vz = (int)fz;
        const float wx = sx - fx,   wy = sy - fy,   wz = sz - fz;

        const float2* __restrict__ table =
            reinterpret_cast<const float2*>(emb) + (size_t)l * HASHMAP_SIZE;
        const float4* __restrict__ table4 =
            reinterpret_cast<const float4*>(table);

        const unsigned r1 = (unsigned)(res + 1);
        const bool dense =
            ((long long)r1 * (long long)r1 * (long long)r1) <= (long long)HASHMAP_SIZE;
        const bool keepL1 = (l <= 2);   // coarse tables fit in L1; keep them resident

        // f[c]: corner order c = (i<<2)|(j<<1)|k  (matches CORNER_OFFSETS)
        float2 f[8];

        if (dense) {
            const unsigned ux = (unsigned)vx, uy = (unsigned)vy, uz = (unsigned)vz;
            const unsigned r1sq = r1 * r1;
            // 4 pairs along z: (i,j,k=0) and (i,j,k=1) are adjacent entries
#pragma unroll
            for (int cp = 0; cp < 4; ++cp) {
                const unsigned ci = (cp >> 1) & 1, cj = cp & 1;
                const unsigned idx = (ux + ci) * r1sq + (uy + cj) * r1 + uz;
                const int c = (ci << 2) | (cj << 1);
                const float4 q = keepL1 ? __ldg(&table4[idx >> 1])
                                        : __ldcg(&table4[idx >> 1]);
                if (idx & 1u) {
                    f[c]     = hi2(q);
                    f[c | 1] = keepL1 ? __ldg(&table[idx + 1])
                                      : __ldcg(&table[idx + 1]);
                } else {
                    f[c]     = lo2(q);
                    f[c | 1] = hi2(q);
                }
            }
        } else {
            const unsigned ux = (unsigned)vx, uy = (unsigned)vy, uz = (unsigned)vz;
            const unsigned hy0 = uy * P2,       hy1 = hy0 + P2;
            const unsigned hz0 = uz * P3,       hz1 = hz0 + P3;
            // hyz[(j<<1)|k]
            const unsigned hyz[4] = { hy0 ^ hz0, hy0 ^ hz1, hy1 ^ hz0, hy1 ^ hz1 };

            if ((ux & 1u) == 0u) {
                // h(ux+1) = h(ux) ^ 1 -> x-pair lives in one aligned float4
#pragma unroll
                for (int cp = 0; cp < 4; ++cp) {
                    const unsigned idx0 = (ux ^ hyz[cp]) & HASH_MASK;
                    const float4 q = __ldcg(&table4[idx0 >> 1]);
                    const int c = cp;          // i=0 corner
                    if (idx0 & 1u) { f[c] = hi2(q); f[c | 4] = lo2(q); }
                    else           { f[c] = lo2(q); f[c | 4] = hi2(q); }
                }
            } else {
#pragma unroll
                for (int cp = 0; cp < 4; ++cp) {
                    const unsigned idx0 = ( ux        ^ hyz[cp]) & HASH_MASK;
                    const unsigned idx1 = ((ux + 1u)  ^ hyz[cp]) & HASH_MASK;
                    f[cp]     = __ldcg(&table[idx0]);
                    f[cp | 4] = __ldcg(&table[idx1]);
                }
            }
        }

        const float omx = 1.0f - wx, omy = 1.0f - wy, omz = 1.0f - wz;

        float c00x = f[0].x * omx + f[4].x * wx;
        float c00y = f[0].y * omx + f[4].y * wx;
        float c01x = f[1].x * omx + f[5].x * wx;
        float c01y = f[1].y * omx + f[5].y * wx;
        float c10x = f[2].x * omx + f[6].x * wx;
        float c10y = f[2].y * omx + f[6].y * wx;
        float c11x = f[3].x * omx + f[7].x * wx;
        float c11y = f[3].y * omx + f[7].y * wx;

        float c0x = c00x * omy + c10x * wy;
        float c0y = c00y * omy + c10y * wy;
        float c1x = c01x * omy + c11x * wy;
        float c1y = c01y * omy + c11y * wy;

        result[2 * l + 0] = c0x * omz + c1x * wz;
        result[2 * l + 1] = c0y * omz + c1y * wz;
    }

    float4* __restrict__ o4 = reinterpret_cast<float4*>(out + (size_t)p * (2 * N_LEVELS));
#pragma unroll
    for (int i = 0; i < 8; ++i) {
        o4[i] = reinterpret_cast<const float4*>(result)[i];
    }
}

extern "C" void kernel_launch(void* const* d_in, const int* in_sizes, int n_in,
                              void* d_out, int out_size)
{
    const float* positions  = (const float*)d_in[0];   // [N_POINTS, 3] f32
    const float* embeddings = (const float*)d_in[1];   // [16, 2^19, 2] f32
    float*       out        = (float*)d_out;           // [N_POINTS, 32] f32

    const int n_points = in_sizes[0] / 3;

    ResTable rt;
    const double scale = exp((log(2048.0) - log(16.0)) / 15.0);
    for (int l = 0; l < N_LEVELS; ++l) {
        rt.res[l] = (int)floor(16.0 * pow(scale, (double)l));
    }

    const int threads = 256;
    const int blocks  = (n_points + threads - 1) / threads;
    hashenc_kernel<<<blocks, threads>>>(positions, embeddings, out, rt, n_points);
}

// round 3
// speedup vs baseline: 1.5354x; 1.5354x over previous
#include <cuda_runtime.h>
#include <math.h>

#define N_LEVELS      16
#define HASHMAP_SIZE  (1u << 19)
#define HASH_MASK     (HASHMAP_SIZE - 1u)
#define P2            2654435761u
#define P3            805459861u

struct ResTable {
    int res[N_LEVELS];
};

__global__ void __launch_bounds__(256, 5)
hashenc_kernel(const float* __restrict__ pos,
               const float* __restrict__ emb,
               float* __restrict__ out,
               ResTable rt,
               int n_points)
{
    int p = blockIdx.x * blockDim.x + threadIdx.x;
    if (p >= n_points) return;

    const float px = pos[p * 3 + 0];
    const float py = pos[p * 3 + 1];
    const float pz = pos[p * 3 + 2];

    float4* __restrict__ o4 = reinterpret_cast<float4*>(out + (size_t)p * (2 * N_LEVELS));

    float2 lv[2];   // results for the current pair of levels

#pragma unroll
    for (int l = 0; l < N_LEVELS; ++l) {
        const int   res  = rt.res[l];
        const float fres = (float)res;

        const float sx = px * fres, sy = py * fres, sz = pz * fres;
        const float fx = floorf(sx), fy = floorf(sy), fz = floorf(sz);
        const int   vx = (int)fx,   vy = (int)fy,   vz = (int)fz;
        const float wx = sx - fx,   wy = sy - fy,   wz = sz - fz;

        const float2* __restrict__ table =
            reinterpret_cast<const float2*>(emb) + (size_t)l * HASHMAP_SIZE;

        const unsigned r1 = (unsigned)(res + 1);
        const bool dense =
            ((long long)r1 * (long long)r1 * (long long)r1) <= (long long)HASHMAP_SIZE;

        // corner order c = (i<<2)|(j<<1)|k, matching CORNER_OFFSETS
        float2 f[8];
#pragma unroll
        for (int c = 0; c < 8; ++c) {
            const int cx = vx + ((c >> 2) & 1);
            const int cy = vy + ((c >> 1) & 1);
            const int cz = vz + (c & 1);
            unsigned idx;
            if (dense) {
                idx = (unsigned)cx * (r1 * r1) + (unsigned)cy * r1 + (unsigned)cz;
            } else {
                const unsigned h = (unsigned)cx * 1u
                                 ^ (unsigned)cy * P2
                                 ^ (unsigned)cz * P3;
                idx = h & HASH_MASK;
            }
            f[c] = __ldg(&table[idx]);
        }

        const float omx = 1.0f - wx, omy = 1.0f - wy, omz = 1.0f - wz;

        float c00x = f[0].x * omx + f[4].x * wx;
        float c00y = f[0].y * omx + f[4].y * wx;
        float c01x = f[1].x * omx + f[5].x * wx;
        float c01y = f[1].y * omx + f[5].y * wx;
        float c10x = f[2].x * omx + f[6].x * wx;
        float c10y = f[2].y * omx + f[6].y * wx;
        float c11x = f[3].x * omx + f[7].x * wx;
        float c11y = f[3].y * omx + f[7].y * wx;

        float c0x = c00x * omy + c10x * wy;
        float c0y = c00y * omy + c10y * wy;
        float c1x = c01x * omy + c11x * wy;
        float c1y = c01y * omy + c11y * wy;

        lv[l & 1] = make_float2(c0x * omz + c1x * wz,
                                c0y * omz + c1y * wz);

        if (l & 1) {
            // stream out two levels as one 16B store; frees the registers
            o4[l >> 1] = make_float4(lv[0].x, lv[0].y, lv[1].x, lv[1].y);
        }
    }
}

extern "C" void kernel_launch(void* const* d_in, const int* in_sizes, int n_in,
                              void* d_out, int out_size)
{
    const float* positions  = (const float*)d_in[0];   // [N_POINTS, 3] f32
    const float* embeddings = (const float*)d_in[1];   // [16, 2^19, 2] f32
    float*       out        = (float*)d_out;           // [N_POINTS, 32] f32

    const int n_points = in_sizes[0] / 3;

    // Mirror numpy exactly in double precision (libm exp/log/pow)
    ResTable rt;
    const double scale = exp((log(2048.0) - log(16.0)) / 15.0);
    for (int l = 0; l < N_LEVELS; ++l) {
        rt.res[l] = (int)floor(16.0 * pow(scale, (double)l));
    }

    const int threads = 256;
    const int blocks  = (n_points + threads - 1) / threads;
    hashenc_kernel<<<blocks, threads>>>(positions, embeddings, out, rt, n_points);
}

// round 4
// speedup vs baseline: 1.6410x; 1.0688x over previous
#include <cuda_runtime.h>
#include <math.h>

#define N_LEVELS      16
#define HASHMAP_SIZE  (1u << 19)
#define HASH_MASK     (HASHMAP_SIZE - 1u)
#define P2            2654435761u
#define P3            805459861u

struct ResTable {
    int res[N_LEVELS];
};

__device__ __forceinline__ float2 lo2(float4 q) { return make_float2(q.x, q.y); }
__device__ __forceinline__ float2 hi2(float4 q) { return make_float2(q.z, q.w); }

// Predicated 8-byte global load: overwrites v only when pred != 0.
// Predicated-off lanes issue no memory transaction (no L1tex wavefront).
__device__ __forceinline__ void pred_ld2(float2& v, unsigned pred, const float2* addr) {
    asm("{\n\t"
        ".reg .pred p;\n\t"
        "setp.ne.u32 p, %2, 0;\n\t"
        "@p ld.global.nc.v2.f32 {%0, %1}, [%3];\n\t"
        "}"
        : "+f"(v.x), "+f"(v.y)
        : "r"(pred), "l"(addr));
}

__global__ void __launch_bounds__(256)
hashenc_kernel(const float* __restrict__ pos,
               const float* __restrict__ emb,
               float* __restrict__ out,
               ResTable rt,
               int n_points)
{
    int p = blockIdx.x * blockDim.x + threadIdx.x;
    if (p >= n_points) return;

    const float px = pos[p * 3 + 0];
    const float py = pos[p * 3 + 1];
    const float pz = pos[p * 3 + 2];

    float result[2 * N_LEVELS];

#pragma unroll
    for (int l = 0; l < N_LEVELS; ++l) {
        const int   res  = rt.res[l];
        const float fres = (float)res;

        const float sx = px * fres, sy = py * fres, sz = pz * fres;
        const float fx = floorf(sx), fy = floorf(sy), fz = floorf(sz);
        const float wx = sx - fx,   wy = sy - fy,   wz = sz - fz;
        const unsigned ux = (unsigned)(int)fx;
        const unsigned uy = (unsigned)(int)fy;
        const unsigned uz = (unsigned)(int)fz;

        const float2* __restrict__ table =
            reinterpret_cast<const float2*>(emb) + (size_t)l * HASHMAP_SIZE;
        const float4* __restrict__ table4 =
            reinterpret_cast<const float4*>(table);

        const unsigned r1 = (unsigned)(res + 1);
        const bool dense =
            ((long long)r1 * (long long)r1 * (long long)r1) <= (long long)HASHMAP_SIZE;

        // f[c]: corner order c = (i<<2)|(j<<1)|k  (matches CORNER_OFFSETS)
        float2 f[8];

        if (dense) {
            // merge z-pairs: corners (i,j,0) and (i,j,1) are adjacent entries
            const unsigned r1sq = r1 * r1;
#pragma unroll
            for (int cp = 0; cp < 4; ++cp) {
                const unsigned ci = (cp >> 1) & 1, cj = cp & 1;
                const unsigned idx = (ux + ci) * r1sq + (uy + cj) * r1 + uz;
                const float4 q = __ldg(&table4[idx >> 1]);
                const unsigned odd = idx & 1u;
                float2 a = odd ? hi2(q) : lo2(q);   // corner k=0 (entry idx)
                float2 b = odd ? lo2(q) : hi2(q);   // entry idx+1 when idx even
                pred_ld2(b, odd, table + idx + 1);  // patch when idx odd
                const int c = (ci << 2) | (cj << 1);
                f[c]     = a;
                f[c | 1] = b;
            }
        } else {
            // merge x-pairs: h(x) = x ^ hyz, so for even x, h(x+1) = h(x)^1
            const unsigned hy0 = uy * P2, hy1 = hy0 + P2;
            const unsigned hz0 = uz * P3, hz1 = hz0 + P3;
            const unsigned hyz[4] = { hy0 ^ hz0, hy0 ^ hz1, hy1 ^ hz0, hy1 ^ hz1 };
            const unsigned xodd = ux & 1u;
#pragma unroll
            for (int cp = 0; cp < 4; ++cp) {
                const unsigned idx0 = (ux ^ hyz[cp]) & HASH_MASK;
                const float4 q = __ldg(&table4[idx0 >> 1]);
                const unsigned odd = idx0 & 1u;
                float2 a = odd ? hi2(q) : lo2(q);   // corner i=0 (entry idx0)
                float2 b = odd ? lo2(q) : hi2(q);   // entry idx0^1 = idx(ux+1) when ux even
                const unsigned idx1 = ((ux + 1u) ^ hyz[cp]) & HASH_MASK;
                pred_ld2(b, xodd, table + idx1);    // patch when ux odd
                f[cp]     = a;                      // c = (0<<2)|(j<<1)|k
                f[cp | 4] = b;                      // c = (1<<2)|(j<<1)|k
            }
        }

        const float omx = 1.0f - wx, omy = 1.0f - wy, omz = 1.0f - wz;

        float c00x = f[0].x * omx + f[4].x * wx;
        float c00y = f[0].y * omx + f[4].y * wx;
        float c01x = f[1].x * omx + f[5].x * wx;
        float c01y = f[1].y * omx + f[5].y * wx;
        float c10x = f[2].x * omx + f[6].x * wx;
        float c10y = f[2].y * omx + f[6].y * wx;
        float c11x = f[3].x * omx + f[7].x * wx;
        float c11y = f[3].y * omx + f[7].y * wx;

        float c0x = c00x * omy + c10x * wy;
        float c0y = c00y * omy + c10y * wy;
        float c1x = c01x * omy + c11x * wy;
        float c1y = c01y * omy + c11y * wy;

        result[2 * l + 0] = c0x * omz + c1x * wz;
        result[2 * l + 1] = c0y * omz + c1y * wz;
    }

    // coalesced 128-byte store per thread (8x float4)
    float4* __restrict__ o4 = reinterpret_cast<float4*>(out + (size_t)p * (2 * N_LEVELS));
#pragma unroll
    for (int i = 0; i < 8; ++i) {
        o4[i] = reinterpret_cast<const float4*>(result)[i];
    }
}

extern "C" void kernel_launch(void* const* d_in, const int* in_sizes, int n_in,
                              void* d_out, int out_size)
{
    const float* positions  = (const float*)d_in[0];   // [N_POINTS, 3] f32
    const float* embeddings = (const float*)d_in[1];   // [16, 2^19, 2] f32
    float*       out        = (float*)d_out;           // [N_POINTS, 32] f32

    const int n_points = in_sizes[0] / 3;

    // Mirror numpy exactly in double precision (libm exp/log/pow)
    ResTable rt;
    const double scale = exp((log(2048.0) - log(16.0)) / 15.0);
    for (int l = 0; l < N_LEVELS; ++l) {
        rt.res[l] = (int)floor(16.0 * pow(scale, (double)l));
    }

    const int threads = 256;
    const int blocks  = (n_points + threads - 1) / threads;
    hashenc_kernel<<<blocks, threads>>>(positions, embeddings, out, rt, n_points);
}

// round 5
// speedup vs baseline: 2.2557x; 1.3746x over previous
#include <cuda_runtime.h>
#include <math.h>

#define N_LEVELS      16
#define HASHMAP_SIZE  (1u << 19)
#define HASH_MASK     (HASHMAP_SIZE - 1u)
#define P2            2654435761u
#define P3            805459861u

struct ResTable {
    int res[N_LEVELS];
};

// 8 lanes per point (one corner each), 4 points per warp.
__global__ void __launch_bounds__(256)
hashenc_kernel(const float* __restrict__ pos,
               const float* __restrict__ emb,
               float* __restrict__ out,
               ResTable rt,
               int n_points)
{
    const int tid    = blockIdx.x * blockDim.x + threadIdx.x;
    const int lane   = threadIdx.x & 31;
    const int c      = lane & 7;        // corner id: (i<<2)|(j<<1)|k
    const int sub    = lane >> 3;       // point slot within warp (0..3)
    const int warpId = tid >> 5;
    const int p      = warpId * 4 + sub;

    const bool valid = (p < n_points);
    const int  pp    = valid ? p : 0;

    // corner offset bits (fixed per lane)
    const unsigned bi = (c >> 2) & 1;   // x offset
    const unsigned bj = (c >> 1) & 1;   // y offset
    const unsigned bk =  c       & 1;   // z offset

    const float px = pos[pp * 3 + 0];
    const float py = pos[pp * 3 + 1];
    const float pz = pos[pp * 3 + 2];

    // lane c keeps results for levels 2c and 2c+1
    float acc0 = 0.f, acc1 = 0.f, acc2 = 0.f, acc3 = 0.f;

#pragma unroll
    for (int l = 0; l < N_LEVELS; ++l) {
        const int   res  = rt.res[l];
        const float fres = (float)res;

        const float sx = px * fres, sy = py * fres, sz = pz * fres;
        const float fx = floorf(sx), fy = floorf(sy), fz = floorf(sz);
        const float wx = sx - fx,   wy = sy - fy,   wz = sz - fz;

        const unsigned ux = (unsigned)(int)fx + bi;
        const unsigned uy = (unsigned)(int)fy + bj;
        const unsigned uz = (unsigned)(int)fz + bk;

        const unsigned r1 = (unsigned)(res + 1);
        const bool dense =
            ((long long)r1 * (long long)r1 * (long long)r1) <= (long long)HASHMAP_SIZE;

        unsigned idx;
        if (dense) {
            idx = ux * (r1 * r1) + uy * r1 + uz;
        } else {
            idx = (ux ^ (uy * P2) ^ (uz * P3)) & HASH_MASK;
        }

        const float2* __restrict__ table =
            reinterpret_cast<const float2*>(emb) + (size_t)l * HASHMAP_SIZE;
        const float2 f = __ldg(&table[idx]);

        // full trilinear weight for this corner
        const float ax = bi ? wx : (1.0f - wx);
        const float ay = bj ? wy : (1.0f - wy);
        const float az = bk ? wz : (1.0f - wz);
        const float w  = ax * ay * az;

        float v0 = f.x * w;
        float v1 = f.y * w;

        // butterfly sum across the 8 corner lanes (stays within the group)
        v0 += __shfl_xor_sync(0xffffffffu, v0, 4);
        v1 += __shfl_xor_sync(0xffffffffu, v1, 4);
        v0 += __shfl_xor_sync(0xffffffffu, v0, 2);
        v1 += __shfl_xor_sync(0xffffffffu, v1, 2);
        v0 += __shfl_xor_sync(0xffffffffu, v0, 1);
        v1 += __shfl_xor_sync(0xffffffffu, v1, 1);

        // lane (l>>1) keeps this level's pair
        if ((l >> 1) == c) {
            if (l & 1) { acc2 = v0; acc3 = v1; }
            else       { acc0 = v0; acc1 = v1; }
        }
    }

    // coalesced store: warp covers 4 consecutive points x 128B
    if (valid) {
        float4* __restrict__ o4 = reinterpret_cast<float4*>(out);
        o4[(size_t)p * 8 + c] = make_float4(acc0, acc1, acc2, acc3);
    }
}

extern "C" void kernel_launch(void* const* d_in, const int* in_sizes, int n_in,
                              void* d_out, int out_size)
{
    const float* positions  = (const float*)d_in[0];   // [N_POINTS, 3] f32
    const float* embeddings = (const float*)d_in[1];   // [16, 2^19, 2] f32
    float*       out        = (float*)d_out;           // [N_POINTS, 32] f32

    const int n_points = in_sizes[0] / 3;

    // Mirror numpy exactly in double precision (libm exp/log/pow)
    ResTable rt;
    const double scale = exp((log(2048.0) - log(16.0)) / 15.0);
    for (int l = 0; l < N_LEVELS; ++l) {
        rt.res[l] = (int)floor(16.0 * pow(scale, (double)l));
    }

    // 8 threads per point
    const long long total_threads = (long long)n_points * 8;
    const int threads = 256;
    const int blocks  = (int)((total_threads + threads - 1) / threads);
    hashenc_kernel<<<blocks, threads>>>(positions, embeddings, out, rt, n_points);
}